// round 1
// baseline (speedup 1.0000x reference)
#include <cuda_runtime.h>
#include <cstdint>

// ---------------------------------------------------------------------------
// WindowAttention (Swin-style shifted window attention), GB300 sm_103a
// Phase 1: qkv = roll(x,-4,-4) @ w_qkv, written in windowed row order (tf32 mma)
// Phase 2: per-window attention (4 heads) + fused output projection + un-roll
// ---------------------------------------------------------------------------

#define N_ROWS 262144          // 16 * 256 * 64  (b, win, token)
__device__ float g_qkv[(size_t)N_ROWS * 384];   // windowed qkv scratch (402 MB)

__device__ __forceinline__ uint32_t f2tf(float f) {
    uint32_t r;
    asm("cvt.rna.tf32.f32 %0, %1;" : "=r"(r) : "f"(f));
    return r;
}

__device__ __forceinline__ void mma8(float* c, const uint32_t* a, const uint32_t* b) {
    asm volatile(
        "mma.sync.aligned.m16n8k8.row.col.f32.tf32.tf32.f32 "
        "{%0,%1,%2,%3}, {%4,%5,%6,%7}, {%8,%9}, {%0,%1,%2,%3};\n"
        : "+f"(c[0]), "+f"(c[1]), "+f"(c[2]), "+f"(c[3])
        : "r"(a[0]), "r"(a[1]), "r"(a[2]), "r"(a[3]), "r"(b[0]), "r"(b[1]));
}

// ===========================================================================
// Kernel 1: QKV GEMM.  M=262144 (windowed rows, gathered from rolled x),
// N=384, K=128.  BM=128, BN=128, BK=32, double-buffered smem, tf32 mma.
// ===========================================================================
#define SA_STR 36
#define SB_STR 132
#define K1_SMEM ((2*128*SA_STR + 2*32*SB_STR) * 4)   // 70656 B

__global__ __launch_bounds__(256, 2)
void qkv_kernel(const float* __restrict__ x, const float* __restrict__ wqkv) {
    extern __shared__ uint32_t sm1[];
    uint32_t* sA = sm1;                       // [2][128][SA_STR]
    uint32_t* sB = sm1 + 2 * 128 * SA_STR;    // [2][32][SB_STR]

    const int t = threadIdx.x;
    const int warp = t >> 5, lane = t & 31;
    const int gid = lane >> 2, tid4 = lane & 3;
    const int bm = blockIdx.x;                 // 0..2047
    const int nbase = blockIdx.y * 128;        // 0,128,256

    // A gather: this thread stages half of one row (row_a), 16 floats
    const int row_a = t >> 1;
    const int r = bm * 128 + row_a;
    const int tok = r & 63, win = (r >> 6) & 255, bb = r >> 14;
    const int wy = win >> 4, wx = win & 15, ty = tok >> 3, tx = tok & 7;
    const int sh = (wy * 8 + ty + 4) & 127, sw = (wx * 8 + tx + 4) & 127;
    const float* aptr = x + (((size_t)bb * 128 + sh) * 128 + sw) * 128 + (t & 1) * 16;

    float4 ra[4], rb[4];

    auto load_regs = [&](int k0) {
        #pragma unroll
        for (int j = 0; j < 4; j++)
            ra[j] = *(const float4*)(aptr + k0 + j * 4);
        #pragma unroll
        for (int j = 0; j < 4; j++) {
            int i = t + 256 * j;
            int rowb = i >> 5, c4 = i & 31;
            rb[j] = *(const float4*)(wqkv + (size_t)(k0 + rowb) * 384 + nbase + c4 * 4);
        }
    };
    auto store_stage = [&](int buf) {
        uint32_t* A = sA + buf * 128 * SA_STR;
        uint32_t* Bm = sB + buf * 32 * SB_STR;
        #pragma unroll
        for (int j = 0; j < 4; j++) {
            uint32_t* p = A + row_a * SA_STR + (t & 1) * 16 + j * 4;
            p[0] = f2tf(ra[j].x); p[1] = f2tf(ra[j].y);
            p[2] = f2tf(ra[j].z); p[3] = f2tf(ra[j].w);
        }
        #pragma unroll
        for (int j = 0; j < 4; j++) {
            int i = t + 256 * j;
            int rowb = i >> 5, c4 = i & 31;
            uint32_t* p = Bm + rowb * SB_STR + c4 * 4;
            p[0] = f2tf(rb[j].x); p[1] = f2tf(rb[j].y);
            p[2] = f2tf(rb[j].z); p[3] = f2tf(rb[j].w);
        }
    };

    load_regs(0);
    store_stage(0);
    __syncthreads();

    const int wm = warp & 3, wn = warp >> 2;    // 4x2 warp grid, warp tile 32x64
    float acc[2][8][4];
    #pragma unroll
    for (int a = 0; a < 2; a++)
        #pragma unroll
        for (int b2 = 0; b2 < 8; b2++)
            #pragma unroll
            for (int c = 0; c < 4; c++) acc[a][b2][c] = 0.f;

    for (int kt = 0; kt < 4; kt++) {
        if (kt < 3) load_regs((kt + 1) * 32);

        const uint32_t* A = sA + (kt & 1) * 128 * SA_STR;
        const uint32_t* Bm = sB + (kt & 1) * 32 * SB_STR;
        #pragma unroll
        for (int kk = 0; kk < 32; kk += 8) {
            uint32_t af[2][4], bf[8][2];
            #pragma unroll
            for (int mt = 0; mt < 2; mt++) {
                int row = wm * 32 + mt * 16 + gid;
                af[mt][0] = A[row * SA_STR + kk + tid4];
                af[mt][1] = A[(row + 8) * SA_STR + kk + tid4];
                af[mt][2] = A[row * SA_STR + kk + tid4 + 4];
                af[mt][3] = A[(row + 8) * SA_STR + kk + tid4 + 4];
            }
            #pragma unroll
            for (int nt = 0; nt < 8; nt++) {
                int col = wn * 64 + nt * 8 + gid;
                bf[nt][0] = Bm[(kk + tid4) * SB_STR + col];
                bf[nt][1] = Bm[(kk + tid4 + 4) * SB_STR + col];
            }
            #pragma unroll
            for (int mt = 0; mt < 2; mt++)
                #pragma unroll
                for (int nt = 0; nt < 8; nt++)
                    mma8(acc[mt][nt], af[mt], bf[nt]);
        }
        if (kt < 3) {
            store_stage((kt + 1) & 1);
            __syncthreads();
        }
    }

    // Epilogue: scatter to windowed qkv buffer
    #pragma unroll
    for (int mt = 0; mt < 2; mt++) {
        int row = bm * 128 + wm * 32 + mt * 16 + gid;
        #pragma unroll
        for (int nt = 0; nt < 8; nt++) {
            int col = nbase + wn * 64 + nt * 8 + tid4 * 2;
            *(float2*)(g_qkv + (size_t)row * 384 + col) =
                make_float2(acc[mt][nt][0], acc[mt][nt][1]);
            *(float2*)(g_qkv + (size_t)(row + 8) * 384 + col) =
                make_float2(acc[mt][nt][2], acc[mt][nt][3]);
        }
    }
}

// ===========================================================================
// Kernel 2: per-window attention + fused output projection + un-roll.
// One block per (b, win). 8 warps: 2 warps per head for attention,
// 2x4 warp grid for the projection GEMM.
// ===========================================================================
// smem (uint32 elements):
//   sV   : [0      , 8448 )  64x132
//   sQ   : [8448   , 16896)  64x132    -- overlaid by sP after S phase
//   sK   : [16896  , 25344)  64x132    -- overlaid by sP after S phase
//   sP   : [8448   , 25856)  4 heads x 64x68
//   pe   : [25600  , 25856)  (dead before sP tail written)   -> place at 25600? NO:
//   (pe placed at 25856, bout at 26112 to avoid sP overlap)
//   phase G: sO at 0 (64x132), sW at 8448 (128x132, ends 25344)
#define PE_OFF   25856
#define BO_OFF   26112
#define K2_ELEMS 26240
#define K2_SMEM  (K2_ELEMS * 4)   // 104960 B

__global__ __launch_bounds__(256, 2)
void attn_kernel(const float* __restrict__ wout, const float* __restrict__ bout,
                 const float* __restrict__ pe,  const float* __restrict__ ul,
                 const float* __restrict__ lr,  float* __restrict__ out) {
    extern __shared__ uint32_t sm2[];
    uint32_t* sV = sm2;
    uint32_t* sQ = sm2 + 64 * 132;
    uint32_t* sK = sm2 + 2 * 64 * 132;
    uint32_t* sP = sm2 + 64 * 132;          // 4 * 64*68, overlays sQ+sK
    uint32_t* sO = sm2;                     // phase G, overlays sV
    uint32_t* sW = sm2 + 64 * 132;          // phase G, overlays sP
    float* sPE = (float*)(sm2 + PE_OFF);
    float* sBO = (float*)(sm2 + BO_OFF);

    const int t = threadIdx.x;
    const int warp = t >> 5, lane = t & 31;
    const int gid = lane >> 2, tid4 = lane & 3;
    const int blk = blockIdx.x;
    const int bb = blk >> 8, win = blk & 255;
    const int wy = win >> 4, wx = win & 15;
    const size_t row0 = ((size_t)bb * 256 + win) * 64;

    // ---- Phase A: load Q, K, V (tf32-converted), pe, b_out ----
    #pragma unroll
    for (int s = 0; s < 3; s++) {
        uint32_t* dst = (s == 0) ? sQ : (s == 1) ? sK : sV;
        const int off = s * 128;
        #pragma unroll
        for (int j = 0; j < 8; j++) {
            int i = t + 256 * j;
            int row = i >> 5, c4 = i & 31;
            float4 v = *(const float4*)(g_qkv + (row0 + row) * 384 + off + c4 * 4);
            uint32_t* p = dst + row * 132 + c4 * 4;
            p[0] = f2tf(v.x); p[1] = f2tf(v.y); p[2] = f2tf(v.z); p[3] = f2tf(v.w);
        }
    }
    if (t < 225) sPE[t] = pe[t];
    if (t < 128) sBO[t] = bout[t];
    __syncthreads();

    // ---- Phase B: S = Q K^T * scale + bias (+ masks), per head ----
    const int head = warp >> 1;
    const int wrb = (warp & 1) * 32;    // warp row base within window
    const int hoff = head * 32;
    float sacc[2][8][4];
    #pragma unroll
    for (int a = 0; a < 2; a++)
        #pragma unroll
        for (int b2 = 0; b2 < 8; b2++)
            #pragma unroll
            for (int c = 0; c < 4; c++) sacc[a][b2][c] = 0.f;

    #pragma unroll
    for (int kk = 0; kk < 32; kk += 8) {
        uint32_t af[2][4], bf[8][2];
        #pragma unroll
        for (int mt = 0; mt < 2; mt++) {
            int row = wrb + mt * 16 + gid;
            af[mt][0] = sQ[row * 132 + hoff + kk + tid4];
            af[mt][1] = sQ[(row + 8) * 132 + hoff + kk + tid4];
            af[mt][2] = sQ[row * 132 + hoff + kk + tid4 + 4];
            af[mt][3] = sQ[(row + 8) * 132 + hoff + kk + tid4 + 4];
        }
        #pragma unroll
        for (int nt = 0; nt < 8; nt++) {
            int key = nt * 8 + gid;
            bf[nt][0] = sK[key * 132 + hoff + kk + tid4];
            bf[nt][1] = sK[key * 132 + hoff + kk + tid4 + 4];
        }
        #pragma unroll
        for (int mt = 0; mt < 2; mt++)
            #pragma unroll
            for (int nt = 0; nt < 8; nt++)
                mma8(sacc[mt][nt], af[mt], bf[nt]);
    }

    // ---- Phase C: bias + masks + softmax (register, shfl over tid4 group) ----
    const float scale = 0.17677669529663689f;
    const bool addUL = (wy == 15);
    const bool addLR = (wx == 15);

    #pragma unroll
    for (int slot = 0; slot < 4; slot++) {
        const int mt = slot >> 1, rh = slot & 1;
        const int i = wrb + mt * 16 + rh * 8 + gid;
        const int iy = i >> 3, ix = i & 7;
        float vrow[16];
        float m = -1e30f;
        #pragma unroll
        for (int nt = 0; nt < 8; nt++) {
            #pragma unroll
            for (int u = 0; u < 2; u++) {
                int j = nt * 8 + tid4 * 2 + u;
                int jy = j >> 3, jx = j & 7;
                float v = sacc[mt][nt][rh * 2 + u] * scale
                        + sPE[(jy - iy + 7) * 15 + (jx - ix + 7)];
                if (addUL) v += ul[i * 64 + j];
                if (addLR) v += lr[i * 64 + j];
                vrow[nt * 2 + u] = v;
                m = fmaxf(m, v);
            }
        }
        m = fmaxf(m, __shfl_xor_sync(0xffffffffu, m, 1));
        m = fmaxf(m, __shfl_xor_sync(0xffffffffu, m, 2));
        float sum = 0.f;
        #pragma unroll
        for (int u2 = 0; u2 < 16; u2++) {
            vrow[u2] = __expf(vrow[u2] - m);
            sum += vrow[u2];
        }
        sum += __shfl_xor_sync(0xffffffffu, sum, 1);
        sum += __shfl_xor_sync(0xffffffffu, sum, 2);
        float inv = 1.f / sum;
        #pragma unroll
        for (int nt = 0; nt < 8; nt++) {
            #pragma unroll
            for (int u = 0; u < 2; u++)
                sacc[mt][nt][rh * 2 + u] = vrow[nt * 2 + u] * inv;
        }
    }
    __syncthreads();   // everyone done reading sQ/sK

    // ---- Phase D: store P (tf32) into sP[head] (overlays sQ/sK) ----
    uint32_t* myP = sP + head * (64 * 68);
    #pragma unroll
    for (int mt = 0; mt < 2; mt++) {
        #pragma unroll
        for (int rh = 0; rh < 2; rh++) {
            int i = wrb + mt * 16 + rh * 8 + gid;
            #pragma unroll
            for (int nt = 0; nt < 8; nt++) {
                int j = nt * 8 + tid4 * 2;
                myP[i * 68 + j]     = f2tf(sacc[mt][nt][rh * 2]);
                myP[i * 68 + j + 1] = f2tf(sacc[mt][nt][rh * 2 + 1]);
            }
        }
    }
    __syncthreads();

    // ---- Phase E: O = P @ V (per head; warp does 32 rows x 32 head-dims) ----
    float oacc[2][4][4];
    #pragma unroll
    for (int a = 0; a < 2; a++)
        #pragma unroll
        for (int b2 = 0; b2 < 4; b2++)
            #pragma unroll
            for (int c = 0; c < 4; c++) oacc[a][b2][c] = 0.f;

    #pragma unroll
    for (int kk = 0; kk < 64; kk += 8) {
        uint32_t af[2][4], bf[4][2];
        #pragma unroll
        for (int mt = 0; mt < 2; mt++) {
            int row = wrb + mt * 16 + gid;
            af[mt][0] = myP[row * 68 + kk + tid4];
            af[mt][1] = myP[(row + 8) * 68 + kk + tid4];
            af[mt][2] = myP[row * 68 + kk + tid4 + 4];
            af[mt][3] = myP[(row + 8) * 68 + kk + tid4 + 4];
        }
        #pragma unroll
        for (int nt = 0; nt < 4; nt++) {
            int d = nt * 8 + gid;
            bf[nt][0] = sV[(kk + tid4) * 132 + hoff + d];
            bf[nt][1] = sV[(kk + tid4 + 4) * 132 + hoff + d];
        }
        #pragma unroll
        for (int mt = 0; mt < 2; mt++)
            #pragma unroll
            for (int nt = 0; nt < 4; nt++)
                mma8(oacc[mt][nt], af[mt], bf[nt]);
    }
    __syncthreads();   // done reading sV and sP

    // ---- Phase F: store O (tf32) to sO [token][head*32+d], overlays sV ----
    #pragma unroll
    for (int mt = 0; mt < 2; mt++) {
        int i = wrb + mt * 16 + gid;
        #pragma unroll
        for (int nt = 0; nt < 4; nt++) {
            int c = hoff + nt * 8 + tid4 * 2;
            sO[i * 132 + c]           = f2tf(oacc[mt][nt][0]);
            sO[i * 132 + c + 1]       = f2tf(oacc[mt][nt][1]);
            sO[(i + 8) * 132 + c]     = f2tf(oacc[mt][nt][2]);
            sO[(i + 8) * 132 + c + 1] = f2tf(oacc[mt][nt][3]);
        }
    }
    // Load full w_out into sW (overlays sP region)
    #pragma unroll
    for (int j = 0; j < 16; j++) {
        int i = t + 256 * j;
        int row = i >> 5, c4 = i & 31;
        float4 v = *(const float4*)(wout + (size_t)row * 128 + c4 * 4);
        uint32_t* p = sW + row * 132 + c4 * 4;
        p[0] = f2tf(v.x); p[1] = f2tf(v.y); p[2] = f2tf(v.z); p[3] = f2tf(v.w);
    }
    __syncthreads();

    // ---- Phase G: Y = O @ w_out + b_out, scatter with un-roll ----
    const int pwm = warp & 1, pwn = warp >> 1;   // 2x4 warp grid, tile 32x32
    float yacc[2][4][4];
    #pragma unroll
    for (int a = 0; a < 2; a++)
        #pragma unroll
        for (int b2 = 0; b2 < 4; b2++)
            #pragma unroll
            for (int c = 0; c < 4; c++) yacc[a][b2][c] = 0.f;

    #pragma unroll
    for (int kk = 0; kk < 128; kk += 8) {
        uint32_t af[2][4], bf[4][2];
        #pragma unroll
        for (int mt = 0; mt < 2; mt++) {
            int row = pwm * 32 + mt * 16 + gid;
            af[mt][0] = sO[row * 132 + kk + tid4];
            af[mt][1] = sO[(row + 8) * 132 + kk + tid4];
            af[mt][2] = sO[row * 132 + kk + tid4 + 4];
            af[mt][3] = sO[(row + 8) * 132 + kk + tid4 + 4];
        }
        #pragma unroll
        for (int nt = 0; nt < 4; nt++) {
            int col = pwn * 32 + nt * 8 + gid;
            bf[nt][0] = sW[(kk + tid4) * 132 + col];
            bf[nt][1] = sW[(kk + tid4 + 4) * 132 + col];
        }
        #pragma unroll
        for (int mt = 0; mt < 2; mt++)
            #pragma unroll
            for (int nt = 0; nt < 4; nt++)
                mma8(yacc[mt][nt], af[mt], bf[nt]);
    }

    #pragma unroll
    for (int mt = 0; mt < 2; mt++) {
        #pragma unroll
        for (int rh = 0; rh < 2; rh++) {
            int i = pwm * 32 + mt * 16 + rh * 8 + gid;
            int ty = i >> 3, tx = i & 7;
            int h = (wy * 8 + ty + 4) & 127;
            int w = (wx * 8 + tx + 4) & 127;
            float* orow = out + (((size_t)bb * 128 + h) * 128 + w) * 128;
            #pragma unroll
            for (int nt = 0; nt < 4; nt++) {
                int c = pwn * 32 + nt * 8 + tid4 * 2;
                float2 v = make_float2(yacc[mt][nt][rh * 2]     + sBO[c],
                                       yacc[mt][nt][rh * 2 + 1] + sBO[c + 1]);
                *(float2*)(orow + c) = v;
            }
        }
    }
}

// ===========================================================================
extern "C" void kernel_launch(void* const* d_in, const int* in_sizes, int n_in,
                              void* d_out, int out_size) {
    const float* x    = (const float*)d_in[0];
    const float* wqkv = (const float*)d_in[1];
    const float* wout = (const float*)d_in[2];
    const float* bout = (const float*)d_in[3];
    const float* pe   = (const float*)d_in[4];
    const float* ul   = (const float*)d_in[5];
    const float* lr   = (const float*)d_in[6];
    float* out = (float*)d_out;

    cudaFuncSetAttribute(qkv_kernel, cudaFuncAttributeMaxDynamicSharedMemorySize, K1_SMEM);
    cudaFuncSetAttribute(attn_kernel, cudaFuncAttributeMaxDynamicSharedMemorySize, K2_SMEM);

    dim3 g1(2048, 3, 1);
    qkv_kernel<<<g1, 256, K1_SMEM>>>(x, wqkv);
    attn_kernel<<<4096, 256, K2_SMEM>>>(wout, bout, pe, ul, lr, out);
}

// round 3
// speedup vs baseline: 1.0852x; 1.0852x over previous
#include <cuda_runtime.h>
#include <cstdint>

// ---------------------------------------------------------------------------
// WindowAttention (Swin-style shifted window attention), GB300 sm_103a
// K0: convert w_qkv / w_out fp32 -> tf32 bit patterns
// K1: qkv = roll(x,-4,-4) @ w_qkv, windowed row order, tf32 output scratch.
//     A tile staged once, 3 N-chunks looped in-block, B via cp.async.
// K2: per-window attention (4 heads) + fused output projection + un-roll.
//     Q/K/V and w_out pulled with cp.async (already tf32).
// ---------------------------------------------------------------------------

#define N_ROWS 262144          // 16 * 256 * 64  (b, win, token)
__device__ uint32_t g_qkv[(size_t)N_ROWS * 384];   // tf32 scratch (402 MB)
__device__ uint32_t g_wqkv_tf[128 * 384];
__device__ uint32_t g_wout_tf[128 * 128];

__device__ __forceinline__ uint32_t f2tf(float f) {
    uint32_t r;
    asm("cvt.rna.tf32.f32 %0, %1;" : "=r"(r) : "f"(f));
    return r;
}

__device__ __forceinline__ uint32_t saddr(const void* p) {
    return (uint32_t)__cvta_generic_to_shared(p);
}
#define CP16(dst, src) \
    asm volatile("cp.async.cg.shared.global [%0], [%1], 16;\n" :: "r"(dst), "l"(src))
#define CP_COMMIT() asm volatile("cp.async.commit_group;\n")

__device__ __forceinline__ void mma8(float* c, const uint32_t* a, const uint32_t* b) {
    asm volatile(
        "mma.sync.aligned.m16n8k8.row.col.f32.tf32.tf32.f32 "
        "{%0,%1,%2,%3}, {%4,%5,%6,%7}, {%8,%9}, {%0,%1,%2,%3};\n"
        : "+f"(c[0]), "+f"(c[1]), "+f"(c[2]), "+f"(c[3])
        : "r"(a[0]), "r"(a[1]), "r"(a[2]), "r"(a[3]), "r"(b[0]), "r"(b[1]));
}

// ===========================================================================
// K0: weight conversion
// ===========================================================================
__global__ void cvt_kernel(const float* __restrict__ wqkv,
                           const float* __restrict__ wout) {
    int i = blockIdx.x * 256 + threadIdx.x;
    if (i < 128 * 384) g_wqkv_tf[i] = f2tf(wqkv[i]);
    if (i < 128 * 128) g_wout_tf[i] = f2tf(wout[i]);
}

// ===========================================================================
// K1: QKV GEMM.  M=262144 (windowed rows gathered from rolled x), N=384, K=128.
// BM=128; full A (128x128) staged once; loop 3 N-chunks of 128; BK=32 B tiles
// double-buffered via cp.async.
// ===========================================================================
#define K1_SMEM ((128*132 + 2*32*132) * 4)   // 101376 B

__global__ __launch_bounds__(256, 2)
void qkv_kernel(const float* __restrict__ x) {
    extern __shared__ uint32_t sm1[];
    uint32_t* sA = sm1;                   // [128][132]
    uint32_t* sB = sm1 + 128 * 132;       // [2][32][132]

    const int t = threadIdx.x;
    const int warp = t >> 5, lane = t & 31;
    const int gid = lane >> 2, tid4 = lane & 3;
    const int bm = blockIdx.x;            // 0..2047

    auto issueB = [&](int tileIdx) {
        const int nb = tileIdx >> 2, kt = tileIdx & 3, buf = tileIdx & 1;
        uint32_t* dstB = sB + buf * (32 * 132);
        #pragma unroll
        for (int jj = 0; jj < 4; jj++) {
            int i = t + 256 * jj;
            int rowb = i >> 5, c16 = i & 31;
            CP16(saddr(dstB + rowb * 132 + c16 * 4),
                 g_wqkv_tf + (kt * 32 + rowb) * 384 + nb * 128 + c16 * 4);
        }
        CP_COMMIT();
    };

    issueB(0);

    // A gather: thread t stages half a row (64 floats) with the roll applied
    {
        const int row_a = t >> 1, half = t & 1;
        const int r = bm * 128 + row_a;
        const int tok = r & 63, win = (r >> 6) & 255, bb = r >> 14;
        const int wy = win >> 4, wx = win & 15, ty = tok >> 3, tx = tok & 7;
        const int sh = (wy * 8 + ty + 4) & 127, sw = (wx * 8 + tx + 4) & 127;
        const float* aptr = x + (((size_t)bb * 128 + sh) * 128 + sw) * 128 + half * 64;
        uint32_t* ap = sA + row_a * 132 + half * 64;
        #pragma unroll
        for (int j = 0; j < 16; j++) {
            float4 v = *(const float4*)(aptr + j * 4);
            ap[j * 4 + 0] = f2tf(v.x); ap[j * 4 + 1] = f2tf(v.y);
            ap[j * 4 + 2] = f2tf(v.z); ap[j * 4 + 3] = f2tf(v.w);
        }
    }

    const int wm = warp & 3, wn = warp >> 2;     // 4x2 warp grid, tile 32x64

    for (int nb = 0; nb < 3; nb++) {
        float acc[2][8][4];
        #pragma unroll
        for (int a = 0; a < 2; a++)
            #pragma unroll
            for (int b2 = 0; b2 < 8; b2++)
                #pragma unroll
                for (int c = 0; c < 4; c++) acc[a][b2][c] = 0.f;

        for (int kt = 0; kt < 4; kt++) {
            const int cur = nb * 4 + kt;
            if (cur + 1 < 12) {
                issueB(cur + 1);
                asm volatile("cp.async.wait_group 1;\n");
            } else {
                asm volatile("cp.async.wait_group 0;\n");
            }
            __syncthreads();

            const uint32_t* Bm = sB + (cur & 1) * (32 * 132);
            #pragma unroll
            for (int kk = 0; kk < 32; kk += 8) {
                uint32_t af[2][4], bf[8][2];
                #pragma unroll
                for (int mt = 0; mt < 2; mt++) {
                    int row = wm * 32 + mt * 16 + gid;
                    int kc = kt * 32 + kk + tid4;
                    af[mt][0] = sA[row * 132 + kc];
                    af[mt][1] = sA[(row + 8) * 132 + kc];
                    af[mt][2] = sA[row * 132 + kc + 4];
                    af[mt][3] = sA[(row + 8) * 132 + kc + 4];
                }
                #pragma unroll
                for (int nt = 0; nt < 8; nt++) {
                    int col = wn * 64 + nt * 8 + gid;
                    bf[nt][0] = Bm[(kk + tid4) * 132 + col];
                    bf[nt][1] = Bm[(kk + tid4 + 4) * 132 + col];
                }
                #pragma unroll
                for (int mt = 0; mt < 2; mt++)
                    #pragma unroll
                    for (int nt = 0; nt < 8; nt++)
                        mma8(acc[mt][nt], af[mt], bf[nt]);
            }
            __syncthreads();   // protect buf before tile cur+2 lands
        }

        // Epilogue for this N-chunk: tf32-convert and scatter
        #pragma unroll
        for (int mt = 0; mt < 2; mt++) {
            int row = bm * 128 + wm * 32 + mt * 16 + gid;
            #pragma unroll
            for (int nt = 0; nt < 8; nt++) {
                int col = nb * 128 + wn * 64 + nt * 8 + tid4 * 2;
                uint2 v0 = make_uint2(f2tf(acc[mt][nt][0]), f2tf(acc[mt][nt][1]));
                uint2 v1 = make_uint2(f2tf(acc[mt][nt][2]), f2tf(acc[mt][nt][3]));
                *(uint2*)(g_qkv + (size_t)row * 384 + col) = v0;
                *(uint2*)(g_qkv + (size_t)(row + 8) * 384 + col) = v1;
            }
        }
    }
}

// ===========================================================================
// K2: per-window attention + fused output projection + un-roll.
// One block per (b, win). 8 warps: 2 warps per head for attention,
// 2x4 warp grid for the projection GEMM.
// ===========================================================================
#define PE_OFF   25856
#define BO_OFF   26112
#define K2_ELEMS 26240
#define K2_SMEM  (K2_ELEMS * 4)   // 104960 B

__global__ __launch_bounds__(256, 2)
void attn_kernel(const float* __restrict__ bout,
                 const float* __restrict__ pe,  const float* __restrict__ ul,
                 const float* __restrict__ lr,  float* __restrict__ out) {
    extern __shared__ uint32_t sm2[];
    uint32_t* sV = sm2;
    uint32_t* sQ = sm2 + 64 * 132;
    uint32_t* sK = sm2 + 2 * 64 * 132;
    uint32_t* sP = sm2 + 64 * 132;          // 4 * 64*68, overlays sQ+sK
    uint32_t* sO = sm2;                     // phase G, overlays sV
    uint32_t* sW = sm2 + 64 * 132;          // phase G, overlays sP
    float* sPE = (float*)(sm2 + PE_OFF);
    float* sBO = (float*)(sm2 + BO_OFF);

    const int t = threadIdx.x;
    const int warp = t >> 5, lane = t & 31;
    const int gid = lane >> 2, tid4 = lane & 3;
    const int blk = blockIdx.x;
    const int bb = blk >> 8, win = blk & 255;
    const int wy = win >> 4, wx = win & 15;
    const size_t row0 = ((size_t)bb * 256 + win) * 64;

    // ---- Phase A: async-load Q, K, V (already tf32), pe, b_out ----
    {
        #pragma unroll
        for (int seg = 0; seg < 3; seg++) {
            uint32_t* dst = (seg == 0) ? sQ : (seg == 1) ? sK : sV;
            #pragma unroll
            for (int jj = 0; jj < 8; jj++) {
                int i = t + 256 * jj;
                int row = i >> 5, c16 = i & 31;
                CP16(saddr(dst + row * 132 + c16 * 4),
                     g_qkv + (row0 + row) * 384 + seg * 128 + c16 * 4);
            }
        }
        CP_COMMIT();
    }
    if (t < 225) sPE[t] = pe[t];
    if (t < 128) sBO[t] = bout[t];
    asm volatile("cp.async.wait_group 0;\n");
    __syncthreads();

    // ---- Phase B: S = Q K^T * scale + bias (+ masks), per head ----
    const int head = warp >> 1;
    const int wrb = (warp & 1) * 32;    // warp row base within window
    const int hoff = head * 32;
    float sacc[2][8][4];
    #pragma unroll
    for (int a = 0; a < 2; a++)
        #pragma unroll
        for (int b2 = 0; b2 < 8; b2++)
            #pragma unroll
            for (int c = 0; c < 4; c++) sacc[a][b2][c] = 0.f;

    #pragma unroll
    for (int kk = 0; kk < 32; kk += 8) {
        uint32_t af[2][4], bf[8][2];
        #pragma unroll
        for (int mt = 0; mt < 2; mt++) {
            int row = wrb + mt * 16 + gid;
            af[mt][0] = sQ[row * 132 + hoff + kk + tid4];
            af[mt][1] = sQ[(row + 8) * 132 + hoff + kk + tid4];
            af[mt][2] = sQ[row * 132 + hoff + kk + tid4 + 4];
            af[mt][3] = sQ[(row + 8) * 132 + hoff + kk + tid4 + 4];
        }
        #pragma unroll
        for (int nt = 0; nt < 8; nt++) {
            int key = nt * 8 + gid;
            bf[nt][0] = sK[key * 132 + hoff + kk + tid4];
            bf[nt][1] = sK[key * 132 + hoff + kk + tid4 + 4];
        }
        #pragma unroll
        for (int mt = 0; mt < 2; mt++)
            #pragma unroll
            for (int nt = 0; nt < 8; nt++)
                mma8(sacc[mt][nt], af[mt], bf[nt]);
    }

    // ---- Phase C: bias + masks + softmax (register, shfl over tid4 group) ----
    const float scale = 0.17677669529663689f;
    const bool addUL = (wy == 15);
    const bool addLR = (wx == 15);

    #pragma unroll
    for (int slot = 0; slot < 4; slot++) {
        const int mt = slot >> 1, rh = slot & 1;
        const int i = wrb + mt * 16 + rh * 8 + gid;
        const int iy = i >> 3, ix = i & 7;
        float vrow[16];
        float m = -1e30f;
        #pragma unroll
        for (int nt = 0; nt < 8; nt++) {
            #pragma unroll
            for (int u = 0; u < 2; u++) {
                int j = nt * 8 + tid4 * 2 + u;
                int jy = j >> 3, jx = j & 7;
                float v = sacc[mt][nt][rh * 2 + u] * scale
                        + sPE[(jy - iy + 7) * 15 + (jx - ix + 7)];
                if (addUL) v += ul[i * 64 + j];
                if (addLR) v += lr[i * 64 + j];
                vrow[nt * 2 + u] = v;
                m = fmaxf(m, v);
            }
        }
        m = fmaxf(m, __shfl_xor_sync(0xffffffffu, m, 1));
        m = fmaxf(m, __shfl_xor_sync(0xffffffffu, m, 2));
        float sum = 0.f;
        #pragma unroll
        for (int u2 = 0; u2 < 16; u2++) {
            vrow[u2] = __expf(vrow[u2] - m);
            sum += vrow[u2];
        }
        sum += __shfl_xor_sync(0xffffffffu, sum, 1);
        sum += __shfl_xor_sync(0xffffffffu, sum, 2);
        float inv = 1.f / sum;
        #pragma unroll
        for (int nt = 0; nt < 8; nt++) {
            #pragma unroll
            for (int u = 0; u < 2; u++)
                sacc[mt][nt][rh * 2 + u] = vrow[nt * 2 + u] * inv;
        }
    }
    __syncthreads();   // everyone done reading sQ/sK

    // ---- Phase D: store P (tf32) into sP[head] (overlays sQ/sK) ----
    uint32_t* myP = sP + head * (64 * 68);
    #pragma unroll
    for (int mt = 0; mt < 2; mt++) {
        #pragma unroll
        for (int rh = 0; rh < 2; rh++) {
            int i = wrb + mt * 16 + rh * 8 + gid;
            #pragma unroll
            for (int nt = 0; nt < 8; nt++) {
                int j = nt * 8 + tid4 * 2;
                myP[i * 68 + j]     = f2tf(sacc[mt][nt][rh * 2]);
                myP[i * 68 + j + 1] = f2tf(sacc[mt][nt][rh * 2 + 1]);
            }
        }
    }
    __syncthreads();

    // ---- Phase E: O = P @ V (per head; warp does 32 rows x 32 head-dims) ----
    float oacc[2][4][4];
    #pragma unroll
    for (int a = 0; a < 2; a++)
        #pragma unroll
        for (int b2 = 0; b2 < 4; b2++)
            #pragma unroll
            for (int c = 0; c < 4; c++) oacc[a][b2][c] = 0.f;

    #pragma unroll
    for (int kk = 0; kk < 64; kk += 8) {
        uint32_t af[2][4], bf[4][2];
        #pragma unroll
        for (int mt = 0; mt < 2; mt++) {
            int row = wrb + mt * 16 + gid;
            af[mt][0] = myP[row * 68 + kk + tid4];
            af[mt][1] = myP[(row + 8) * 68 + kk + tid4];
            af[mt][2] = myP[row * 68 + kk + tid4 + 4];
            af[mt][3] = myP[(row + 8) * 68 + kk + tid4 + 4];
        }
        #pragma unroll
        for (int nt = 0; nt < 4; nt++) {
            int d = nt * 8 + gid;
            bf[nt][0] = sV[(kk + tid4) * 132 + hoff + d];
            bf[nt][1] = sV[(kk + tid4 + 4) * 132 + hoff + d];
        }
        #pragma unroll
        for (int mt = 0; mt < 2; mt++)
            #pragma unroll
            for (int nt = 0; nt < 4; nt++)
                mma8(oacc[mt][nt], af[mt], bf[nt]);
    }
    __syncthreads();   // done reading sV and sP

    // ---- Phase F: async-fetch w_out, store O (tf32) to sO [token][128] ----
    #pragma unroll
    for (int jj = 0; jj < 16; jj++) {
        int i = t + 256 * jj;
        int row = i >> 5, c16 = i & 31;
        CP16(saddr(sW + row * 132 + c16 * 4), g_wout_tf + row * 128 + c16 * 4);
    }
    CP_COMMIT();

    #pragma unroll
    for (int mt = 0; mt < 2; mt++) {
        int i = wrb + mt * 16 + gid;
        #pragma unroll
        for (int nt = 0; nt < 4; nt++) {
            int c = hoff + nt * 8 + tid4 * 2;
            sO[i * 132 + c]           = f2tf(oacc[mt][nt][0]);
            sO[i * 132 + c + 1]       = f2tf(oacc[mt][nt][1]);
            sO[(i + 8) * 132 + c]     = f2tf(oacc[mt][nt][2]);
            sO[(i + 8) * 132 + c + 1] = f2tf(oacc[mt][nt][3]);
        }
    }
    asm volatile("cp.async.wait_group 0;\n");
    __syncthreads();

    // ---- Phase G: Y = O @ w_out + b_out, scatter with un-roll ----
    const int pwm = warp & 1, pwn = warp >> 1;   // 2x4 warp grid, tile 32x32
    float yacc[2][4][4];
    #pragma unroll
    for (int a = 0; a < 2; a++)
        #pragma unroll
        for (int b2 = 0; b2 < 4; b2++)
            #pragma unroll
            for (int c = 0; c < 4; c++) yacc[a][b2][c] = 0.f;

    #pragma unroll
    for (int kk = 0; kk < 128; kk += 8) {
        uint32_t af[2][4], bf[4][2];
        #pragma unroll
        for (int mt = 0; mt < 2; mt++) {
            int row = pwm * 32 + mt * 16 + gid;
            af[mt][0] = sO[row * 132 + kk + tid4];
            af[mt][1] = sO[(row + 8) * 132 + kk + tid4];
            af[mt][2] = sO[row * 132 + kk + tid4 + 4];
            af[mt][3] = sO[(row + 8) * 132 + kk + tid4 + 4];
        }
        #pragma unroll
        for (int nt = 0; nt < 4; nt++) {
            int col = pwn * 32 + nt * 8 + gid;
            bf[nt][0] = sW[(kk + tid4) * 132 + col];
            bf[nt][1] = sW[(kk + tid4 + 4) * 132 + col];
        }
        #pragma unroll
        for (int mt = 0; mt < 2; mt++)
            #pragma unroll
            for (int nt = 0; nt < 4; nt++)
                mma8(yacc[mt][nt], af[mt], bf[nt]);
    }

    #pragma unroll
    for (int mt = 0; mt < 2; mt++) {
        #pragma unroll
        for (int rh = 0; rh < 2; rh++) {
            int i = pwm * 32 + mt * 16 + rh * 8 + gid;
            int ty = i >> 3, tx = i & 7;
            int h = (wy * 8 + ty + 4) & 127;
            int w = (wx * 8 + tx + 4) & 127;
            float* orow = out + (((size_t)bb * 128 + h) * 128 + w) * 128;
            #pragma unroll
            for (int nt = 0; nt < 4; nt++) {
                int c = pwn * 32 + nt * 8 + tid4 * 2;
                float2 v = make_float2(yacc[mt][nt][rh * 2]     + sBO[c],
                                       yacc[mt][nt][rh * 2 + 1] + sBO[c + 1]);
                *(float2*)(orow + c) = v;
            }
        }
    }
}

// ===========================================================================
extern "C" void kernel_launch(void* const* d_in, const int* in_sizes, int n_in,
                              void* d_out, int out_size) {
    const float* x    = (const float*)d_in[0];
    const float* wqkv = (const float*)d_in[1];
    const float* wout = (const float*)d_in[2];
    const float* bout = (const float*)d_in[3];
    const float* pe   = (const float*)d_in[4];
    const float* ul   = (const float*)d_in[5];
    const float* lr   = (const float*)d_in[6];
    float* out = (float*)d_out;

    cudaFuncSetAttribute(qkv_kernel, cudaFuncAttributeMaxDynamicSharedMemorySize, K1_SMEM);
    cudaFuncSetAttribute(attn_kernel, cudaFuncAttributeMaxDynamicSharedMemorySize, K2_SMEM);

    cvt_kernel<<<192, 256>>>(wqkv, wout);
    qkv_kernel<<<2048, 256, K1_SMEM>>>(x);
    attn_kernel<<<4096, 256, K2_SMEM>>>(bout, pe, ul, lr, out);
}